// round 1
// baseline (speedup 1.0000x reference)
#include <cuda_runtime.h>

#define Nn 20000
#define Ee 640000
#define Hh 128
#define NODE_F 16
#define EDGE_F 8
#define MSG_IN 267

#define TILE 64
#define NT 256
#define KS 8
#define SIN_STRIDE 272
#define SA_STRIDE 132
#define SC_STRIDE 260

// ---------------- device scratch (allocation-free rule) ----------------
__device__ float g_h[2][Nn * Hh];   // ping-pong hidden states
__device__ float g_msum[Nn * Hh];   // per-node message sum
__device__ float g_fsum[Nn * 9];    // per-node f sum
__device__ float g_cnt[Nn];         // per-node edge count (row)
__device__ float g_equ[Nn * 9];     // current equ

// ---------------- helpers ----------------
__device__ __forceinline__ float silu(float x) {
    return x * __frcp_rn(1.f + __expf(-x));
}

__device__ __forceinline__ unsigned long long fma2(unsigned long long a,
                                                   unsigned long long b,
                                                   unsigned long long c) {
    unsigned long long d;
    asm("fma.rn.f32x2 %0, %1, %2, %3;" : "=l"(d) : "l"(a), "l"(b), "l"(c));
    return d;
}
__device__ __forceinline__ unsigned long long pack2(float x) {
    unsigned long long d;
    asm("mov.b64 %0, {%1, %1};" : "=l"(d) : "f"(x));
    return d;
}
__device__ __forceinline__ float2 unpack2(unsigned long long v) {
    float2 r;
    asm("mov.b64 {%0, %1}, %2;" : "=f"(r.x), "=f"(r.y) : "l"(v));
    return r;
}

// ---------------- 64-row tile GEMM: out[64][128] = act(in[64][kdim] @ W + b) ----------------
// W is [kdim x 128] row-major in global (L2-resident). PERM applies the
// msg_W1 row reorder (our s_in layout = [h_row, h_col, ef, scalar]).
template <bool PERM, bool ACT>
__device__ __forceinline__ void gemm_tile(const float* sInp, int inStride,
                                          const float* __restrict__ W,
                                          const float* __restrict__ bias,
                                          int kdim, float* sOut, int outStride,
                                          float* wslab, int tid) {
    const int tx = tid & 15;   // 8 output cols
    const int ty = tid >> 4;   // 4 rows
    unsigned long long acc[4][4];
#pragma unroll
    for (int i = 0; i < 4; i++)
#pragma unroll
        for (int p = 0; p < 4; p++) acc[i][p] = 0ull;

    for (int k0 = 0; k0 < kdim; k0 += KS) {
        // stage KS x 128 weight slab (1024 floats, one float4 per thread)
        {
            int li = tid * 4;
            int rr = li >> 7, cc = li & 127;
            int gk = k0 + rr;
            float4 v = make_float4(0.f, 0.f, 0.f, 0.f);
            if (gk < kdim) {
                int src = PERM ? (gk < 264 ? gk + 3 : gk - 264) : gk;
                v = *(const float4*)(W + src * 128 + cc);
            }
            *(float4*)(wslab + rr * 128 + cc) = v;
        }
        __syncthreads();
        int kend = min(KS, kdim - k0);
        if (kend == KS) {
#pragma unroll
            for (int kk = 0; kk < KS; kk++) {
                unsigned long long ap[4];
#pragma unroll
                for (int i = 0; i < 4; i++)
                    ap[i] = pack2(sInp[(ty * 4 + i) * inStride + k0 + kk]);
                const ulonglong2* wp =
                    (const ulonglong2*)(wslab + kk * 128 + tx * 8);
                ulonglong2 b01 = wp[0];
                ulonglong2 b23 = wp[1];
#pragma unroll
                for (int i = 0; i < 4; i++) {
                    acc[i][0] = fma2(ap[i], b01.x, acc[i][0]);
                    acc[i][1] = fma2(ap[i], b01.y, acc[i][1]);
                    acc[i][2] = fma2(ap[i], b23.x, acc[i][2]);
                    acc[i][3] = fma2(ap[i], b23.y, acc[i][3]);
                }
            }
        } else {
            for (int kk = 0; kk < kend; kk++) {
                unsigned long long ap[4];
#pragma unroll
                for (int i = 0; i < 4; i++)
                    ap[i] = pack2(sInp[(ty * 4 + i) * inStride + k0 + kk]);
                const ulonglong2* wp =
                    (const ulonglong2*)(wslab + kk * 128 + tx * 8);
                ulonglong2 b01 = wp[0];
                ulonglong2 b23 = wp[1];
#pragma unroll
                for (int i = 0; i < 4; i++) {
                    acc[i][0] = fma2(ap[i], b01.x, acc[i][0]);
                    acc[i][1] = fma2(ap[i], b01.y, acc[i][1]);
                    acc[i][2] = fma2(ap[i], b23.x, acc[i][2]);
                    acc[i][3] = fma2(ap[i], b23.y, acc[i][3]);
                }
            }
        }
        __syncthreads();
    }
    // bias + activation + write (all k-loops done; input buffer now dead)
    float2 bb[4];
#pragma unroll
    for (int p = 0; p < 4; p++) bb[p] = *(const float2*)(bias + tx * 8 + p * 2);
#pragma unroll
    for (int i = 0; i < 4; i++) {
        float* orow = sOut + (ty * 4 + i) * outStride + tx * 8;
#pragma unroll
        for (int p = 0; p < 4; p++) {
            float2 v = unpack2(acc[i][p]);
            v.x += bb[p].x;
            v.y += bb[p].y;
            if (ACT) { v.x = silu(v.x); v.y = silu(v.y); }
            *(float2*)(orow + p * 2) = v;
        }
    }
    __syncthreads();
}

// ---------------- fused edge kernel ----------------
// per CTA: 64 edges. gather -> msgMLP(267->128->128, silu both) ->
// coordMLP(128->128 silu, ->1 dot) -> atomics (fsum, msum)
extern "C" __global__ void __launch_bounds__(NT) edge_kernel(
    int hbuf, const float* __restrict__ edge_fea, const int* __restrict__ erow,
    const int* __restrict__ ecol, const float* __restrict__ mW1,
    const float* __restrict__ mb1, const float* __restrict__ mW2,
    const float* __restrict__ mb2, const float* __restrict__ cW1,
    const float* __restrict__ cb1, const float* __restrict__ cW2,
    const float* __restrict__ cb2) {
    extern __shared__ float sm[];
    float* sIn = sm;                            // 64 x 272
    float* sA = sIn + TILE * SIN_STRIDE;        // 64 x 132
    float* wslab = sA + TILE * SA_STRIDE;       // 8 x 128
    float* sRij = wslab + KS * 128;             // 64 x 9
    float* sCm = sRij + TILE * 9;               // 64
    float* sW2c = sCm + TILE;                   // 128
    int* sRow = (int*)(sW2c + 128);             // 64

    const int tid = threadIdx.x;
    const int w = tid >> 5, lane = tid & 31;
    const float* hcur = g_h[hbuf];
    const int eb = blockIdx.x * TILE;

    if (tid < 128) sW2c[tid] = cW2[tid];

    // ---- gather phase: each warp handles 8 edges ----
#pragma unroll
    for (int i = 0; i < 8; i++) {
        int el = w * 8 + i;
        int e = eb + el;
        int r = erow[e], c = ecol[e];
        if (lane == 0) sRow[el] = r;
        float4 hv = ((const float4*)(hcur + (size_t)r * Hh))[lane];
        *(float4*)(sIn + el * SIN_STRIDE + lane * 4) = hv;
        float4 hc = ((const float4*)(hcur + (size_t)c * Hh))[lane];
        *(float4*)(sIn + el * SIN_STRIDE + 128 + lane * 4) = hc;
        if (lane < 2) {
            float4 ef = ((const float4*)(edge_fea + (size_t)e * EDGE_F))[lane];
            *(float4*)(sIn + el * SIN_STRIDE + 256 + lane * 4) = ef;
        }
        if (lane < 9) {
            float rv = g_equ[r * 9 + lane] - g_equ[c * 9 + lane];
            sRij[el * 9 + lane] = rv;
        }
        __syncwarp();
        if (lane < 3) {
            float a = sRij[el * 9 + lane];
            float b = sRij[el * 9 + 3 + lane];
            float c2 = sRij[el * 9 + 6 + lane];
            sIn[el * SIN_STRIDE + 264 + lane] = sqrtf(a * a + b * b + c2 * c2);
        }
    }
    __syncthreads();

    // y1 = silu(s_in @ mW1 + b1)  (PERM maps our layout to msg_W1 row order)
    gemm_tile<true, true>(sIn, SIN_STRIDE, mW1, mb1, MSG_IN, sA, SA_STRIDE, wslab, tid);
    // message = silu(y1 @ mW2 + b2)  -> stored into sIn cols [0,128)
    gemm_tile<false, true>(sA, SA_STRIDE, mW2, mb2, 128, sIn, SIN_STRIDE, wslab, tid);
    // c1 = silu(message @ cW1 + cb1)
    gemm_tile<false, true>(sIn, SIN_STRIDE, cW1, cb1, 128, sA, SA_STRIDE, wslab, tid);

    // coord scalar: cm[e] = dot(c1[e], cW2) + cb2   (4 lanes per edge)
    {
        int el = w * 8 + (lane >> 2);
        int part = lane & 3;
        const float* base = sA + el * SA_STRIDE + part * 32;
        const float* wb = sW2c + part * 32;
        float s = 0.f;
#pragma unroll
        for (int q = 0; q < 32; q++) s += base[q] * wb[q];
        s += __shfl_xor_sync(0xffffffffu, s, 1);
        s += __shfl_xor_sync(0xffffffffu, s, 2);
        if (part == 0) sCm[el] = s + cb2[0];
    }
    __syncthreads();

    // ---- scatter phase ----
    for (int idx = tid; idx < TILE * 9; idx += NT) {
        int el = idx / 9, cpt = idx - el * 9;
        float f = sRij[el * 9 + cpt] * sCm[el];
        atomicAdd(&g_fsum[(size_t)sRow[el] * 9 + cpt], f);
    }
    for (int t = tid; t < TILE * 32; t += NT) {
        int el = t >> 5, q = t & 31;
        float4 m = *(const float4*)(sIn + el * SIN_STRIDE + q * 4);
        float* dst = &g_msum[(size_t)sRow[el] * Hh + q * 4];
        asm volatile("red.global.add.v4.f32 [%0], {%1,%2,%3,%4};" ::"l"(dst),
                     "f"(m.x), "f"(m.y), "f"(m.z), "f"(m.w)
                     : "memory");
    }
}

// ---------------- fused node kernel ----------------
// per CTA: 64 nodes. gate MLP -> equ update -> node MLP -> h_next
extern "C" __global__ void __launch_bounds__(NT) node_kernel(
    int hin, int hout, const float* __restrict__ nW1,
    const float* __restrict__ nb1, const float* __restrict__ nW2,
    const float* __restrict__ nb2, const float* __restrict__ qW1,
    const float* __restrict__ qb1, const float* __restrict__ qW2,
    const float* __restrict__ qb2) {
    extern __shared__ float sm[];
    float* sC = sm;                       // 64 x 260 (concat h, msum)
    float* sA = sC + TILE * SC_STRIDE;    // 64 x 132
    float* wslab = sA + TILE * SA_STRIDE; // 8 x 128
    float* sGate = wslab + KS * 128;      // 64
    float* sW2q = sGate + TILE;           // 128

    const int tid = threadIdx.x;
    const int w = tid >> 5, lane = tid & 31;
    const float* hcur = g_h[hin];
    float* hnext = g_h[hout];
    const int nb = blockIdx.x * TILE;

    if (tid < 128) sW2q[tid] = qW2[tid];

#pragma unroll
    for (int i = 0; i < 8; i++) {
        int nl = w * 8 + i;
        int n = nb + nl;
        float4 hv = make_float4(0.f, 0.f, 0.f, 0.f);
        float4 mv = make_float4(0.f, 0.f, 0.f, 0.f);
        if (n < Nn) {
            hv = ((const float4*)(hcur + (size_t)n * Hh))[lane];
            mv = ((const float4*)(g_msum + (size_t)n * Hh))[lane];
        }
        *(float4*)(sC + nl * SC_STRIDE + lane * 4) = hv;
        *(float4*)(sC + nl * SC_STRIDE + 128 + lane * 4) = mv;
    }
    __syncthreads();

    // gate hidden = silu(h @ qW1 + qb1)
    gemm_tile<false, true>(sC, SC_STRIDE, qW1, qb1, 128, sA, SA_STRIDE, wslab, tid);
    {
        int nl = w * 8 + (lane >> 2);
        int part = lane & 3;
        const float* base = sA + nl * SA_STRIDE + part * 32;
        const float* wb = sW2q + part * 32;
        float s = 0.f;
#pragma unroll
        for (int q = 0; q < 32; q++) s += base[q] * wb[q];
        s += __shfl_xor_sync(0xffffffffu, s, 1);
        s += __shfl_xor_sync(0xffffffffu, s, 2);
        if (part == 0) sGate[nl] = s + qb2[0];
    }
    __syncthreads();

    // equ update: equ = gate*equ + clip(fsum/max(cnt,1))
    for (int idx = tid; idx < TILE * 9; idx += NT) {
        int nl = idx / 9, cpt = idx - nl * 9;
        int n = nb + nl;
        if (n < Nn) {
            float cnt = g_cnt[n];
            float inv = 1.f / fmaxf(cnt, 1.f);
            float tf = g_fsum[n * 9 + cpt] * inv;
            tf = fminf(fmaxf(tf, -100.f), 100.f);
            g_equ[n * 9 + cpt] = sGate[nl] * g_equ[n * 9 + cpt] + tf;
        }
    }

    // node MLP: y = silu(concat @ nW1 + nb1); h = y @ nW2 + nb2
    gemm_tile<false, true>(sC, SC_STRIDE, nW1, nb1, 256, sA, SA_STRIDE, wslab, tid);
    gemm_tile<false, false>(sA, SA_STRIDE, nW2, nb2, 128, sC, SC_STRIDE, wslab, tid);

#pragma unroll
    for (int i = 0; i < 8; i++) {
        int nl = w * 8 + i;
        int n = nb + nl;
        if (n < Nn) {
            float4 v = *(const float4*)(sC + nl * SC_STRIDE + lane * 4);
            ((float4*)(hnext + (size_t)n * Hh))[lane] = v;
        }
    }
}

// ---------------- small kernels ----------------
extern "C" __global__ void init_kernel(const float* __restrict__ equ_in) {
    int i = blockIdx.x * blockDim.x + threadIdx.x;
    if (i < Nn * 9) g_equ[i] = equ_in[i];
    if (i < Nn) g_cnt[i] = 0.f;
}

extern "C" __global__ void count_kernel(const int* __restrict__ erow) {
    int i = blockIdx.x * blockDim.x + threadIdx.x;
    if (i < Ee) atomicAdd(&g_cnt[erow[i]], 1.f);
}

extern "C" __global__ void embed_kernel(const float* __restrict__ h_in,
                                        const float* __restrict__ W,
                                        const float* __restrict__ b) {
    int n = blockIdx.x * 2 + (threadIdx.x >> 7);
    int j = threadIdx.x & 127;
    if (n >= Nn) return;
    float acc = b[j];
#pragma unroll
    for (int k = 0; k < NODE_F; k++) acc += h_in[n * NODE_F + k] * W[k * 128 + j];
    g_h[0][(size_t)n * Hh + j] = acc;
}

extern "C" __global__ void zero_acc_kernel() {
    int i = blockIdx.x * blockDim.x + threadIdx.x;
    if (i < Nn * Hh) g_msum[i] = 0.f;
    else if (i < Nn * Hh + Nn * 9) g_fsum[i - Nn * Hh] = 0.f;
}

extern "C" __global__ void final_copy_kernel(float* __restrict__ out, int out_size) {
    int i = blockIdx.x * blockDim.x + threadIdx.x;
    int tot = Nn * 9 + Nn * Hh;
    if (i >= tot || i >= out_size) return;
    out[i] = (i < Nn * 9) ? g_equ[i] : g_h[0][i - Nn * 9];
}

// ---------------- launch ----------------
extern "C" void kernel_launch(void* const* d_in, const int* in_sizes, int n_in,
                              void* d_out, int out_size) {
    const float* equ = (const float*)d_in[0];
    const float* h_in = (const float*)d_in[1];
    const float* edge_fea = (const float*)d_in[2];
    const float* embW = (const float*)d_in[3];
    const float* embB = (const float*)d_in[4];
    const float* mW1 = (const float*)d_in[5];
    const float* mb1 = (const float*)d_in[6];
    const float* mW2 = (const float*)d_in[7];
    const float* mb2 = (const float*)d_in[8];
    const float* cW1 = (const float*)d_in[9];
    const float* cb1 = (const float*)d_in[10];
    const float* cW2 = (const float*)d_in[11];
    const float* cb2 = (const float*)d_in[12];
    const float* nW1 = (const float*)d_in[13];
    const float* nb1 = (const float*)d_in[14];
    const float* nW2 = (const float*)d_in[15];
    const float* nb2 = (const float*)d_in[16];
    const float* qW1 = (const float*)d_in[17];
    const float* qb1 = (const float*)d_in[18];
    const float* qW2 = (const float*)d_in[19];
    const float* qb2 = (const float*)d_in[20];
    const int* ei = (const int*)d_in[21];
    const int* erow = ei;
    const int* ecol = ei + Ee;

    const int EDGE_SMEM = (TILE * SIN_STRIDE + TILE * SA_STRIDE + KS * 128 +
                           TILE * 9 + TILE + 128 + TILE) * 4;   // 110,848 B
    const int NODE_SMEM = (TILE * SC_STRIDE + TILE * SA_STRIDE + KS * 128 +
                           TILE + 128) * 4;                     // 105,216 B
    cudaFuncSetAttribute(edge_kernel, cudaFuncAttributeMaxDynamicSharedMemorySize, EDGE_SMEM);
    cudaFuncSetAttribute(node_kernel, cudaFuncAttributeMaxDynamicSharedMemorySize, NODE_SMEM);

    init_kernel<<<(Nn * 9 + 255) / 256, 256>>>(equ);
    count_kernel<<<(Ee + 255) / 256, 256>>>(erow);
    embed_kernel<<<Nn / 2, 256>>>(h_in, embW, embB);

    for (int L = 0; L < 2; L++) {
        zero_acc_kernel<<<(Nn * Hh + Nn * 9 + 255) / 256, 256>>>();
        edge_kernel<<<Ee / TILE, NT, EDGE_SMEM>>>(
            L, edge_fea, erow, ecol,
            mW1 + (size_t)L * MSG_IN * 128, mb1 + L * 128,
            mW2 + (size_t)L * 128 * 128, mb2 + L * 128,
            cW1 + (size_t)L * 128 * 128, cb1 + L * 128,
            cW2 + (size_t)L * 128, cb2 + L);
        node_kernel<<<(Nn + TILE - 1) / TILE, NT, NODE_SMEM>>>(
            L, 1 - L,
            nW1 + (size_t)L * 256 * 128, nb1 + L * 128,
            nW2 + (size_t)L * 128 * 128, nb2 + L * 128,
            qW1 + (size_t)L * 128 * 128, qb1 + L * 128,
            qW2 + (size_t)L * 128, qb2 + L);
    }

    final_copy_kernel<<<(Nn * 9 + Nn * Hh + 255) / 256, 256>>>((float*)d_out, out_size);
}

// round 2
// speedup vs baseline: 1.1561x; 1.1561x over previous
#include <cuda_runtime.h>
#include <cstdint>

#define Nn 20000
#define Ee 640000
#define Hh 128
#define NODE_F 16
#define EDGE_F 8
#define MSG_IN 267

#define TILE 64
#define NT 256
#define KS 8
#define SIN_STRIDE 272
#define SA_STRIDE 132
#define SC_STRIDE 260

// ---------------- device scratch ----------------
__device__ float g_h[2][Nn * Hh];
__device__ float g_msum[Nn * Hh];
__device__ float g_fsum[Nn * 9];
__device__ float g_cnt[Nn];
__device__ float g_equ[Nn * 9];

// ---------------- helpers ----------------
__device__ __forceinline__ float silu(float x) {
    return x * __frcp_rn(1.f + __expf(-x));
}
__device__ __forceinline__ unsigned long long fma2(unsigned long long a,
                                                   unsigned long long b,
                                                   unsigned long long c) {
    unsigned long long d;
    asm("fma.rn.f32x2 %0, %1, %2, %3;" : "=l"(d) : "l"(a), "l"(b), "l"(c));
    return d;
}
__device__ __forceinline__ unsigned long long pack2(float x) {
    unsigned long long d;
    asm("mov.b64 %0, {%1, %1};" : "=l"(d) : "f"(x));
    return d;
}
__device__ __forceinline__ float2 unpack2(unsigned long long v) {
    float2 r;
    asm("mov.b64 {%0, %1}, %2;" : "=f"(r.x), "=f"(r.y) : "l"(v));
    return r;
}
__device__ __forceinline__ void cpasync16(uint32_t dst, const void* src) {
    asm volatile("cp.async.ca.shared.global [%0], [%1], 16;" ::"r"(dst),
                 "l"(src) : "memory");
}
__device__ __forceinline__ void cpcommit() {
    asm volatile("cp.async.commit_group;" ::: "memory");
}
template <int N>
__device__ __forceinline__ void cpwait() {
    asm volatile("cp.async.wait_group %0;" ::"n"(N) : "memory");
}

// stage one KS x 128 weight slab into wbuf via cp.async (zero-fill tail rows)
template <bool PERM>
__device__ __forceinline__ void stage_slab(const float* __restrict__ W, int kdim,
                                           int s, float* wbuf, uint32_t wbuf_sh,
                                           int rr, int cc) {
    int gk = s * KS + rr;
    if (gk < kdim) {
        int src = PERM ? (gk < 264 ? gk + 3 : gk - 264) : gk;
        cpasync16(wbuf_sh + (rr * 128 + cc) * 4, W + src * 128 + cc);
    } else {
        *(float4*)(wbuf + rr * 128 + cc) = make_float4(0.f, 0.f, 0.f, 0.f);
    }
    cpcommit();
}

// ---------------- 64-row tile GEMM with double-buffered weight slabs ----------
// out[64][128] = act(in[64][kdim] @ W + b); W row-major [kdim x 128] in global.
template <bool PERM, bool ACT>
__device__ __forceinline__ void gemm_tile(const float* sInp, int inStride,
                                          const float* __restrict__ W,
                                          const float* __restrict__ bias,
                                          int kdim, float* sOut, int outStride,
                                          float* wslab, uint32_t wslab_sh,
                                          int tid) {
    const int tx = tid & 15;        // 16 col groups of 8
    const int ty = tid >> 4;        // 16 row groups of 4
    const int rr = tid >> 5;        // slab stage row
    const int cc = (tid * 4) & 127; // slab stage col
    unsigned long long acc[4][4];
#pragma unroll
    for (int i = 0; i < 4; i++)
#pragma unroll
        for (int p = 0; p < 4; p++) acc[i][p] = 0ull;

    const int nslab = (kdim + KS - 1) / KS;
    stage_slab<PERM>(W, kdim, 0, wslab, wslab_sh, rr, cc);

    for (int s = 0; s < nslab; s++) {
        const int cur = s & 1;
        if (s + 1 < nslab)
            stage_slab<PERM>(W, kdim, s + 1, wslab + (cur ^ 1) * (KS * 128),
                             wslab_sh + (cur ^ 1) * (KS * 128 * 4), rr, cc);
        // hoist this slab's inputs into registers (sInp is stable)
        float4 av[4][2];
#pragma unroll
        for (int i = 0; i < 4; i++) {
            const float* rp = sInp + (ty * 4 + i) * inStride + s * KS;
            av[i][0] = *(const float4*)(rp);
            av[i][1] = *(const float4*)(rp + 4);
        }
        if (s + 1 < nslab) cpwait<1>();
        else cpwait<0>();
        __syncthreads();
        const float* wb = wslab + cur * (KS * 128);
#pragma unroll
        for (int kk = 0; kk < KS; kk++) {
            unsigned long long ap[4];
#pragma unroll
            for (int i = 0; i < 4; i++) {
                float v;
                if ((kk & 3) == 0) v = av[i][kk >> 2].x;
                else if ((kk & 3) == 1) v = av[i][kk >> 2].y;
                else if ((kk & 3) == 2) v = av[i][kk >> 2].z;
                else v = av[i][kk >> 2].w;
                ap[i] = pack2(v);
            }
            const ulonglong2* wp = (const ulonglong2*)(wb + kk * 128 + tx * 8);
            ulonglong2 b01 = wp[0];
            ulonglong2 b23 = wp[1];
#pragma unroll
            for (int i = 0; i < 4; i++) {
                acc[i][0] = fma2(ap[i], b01.x, acc[i][0]);
                acc[i][1] = fma2(ap[i], b01.y, acc[i][1]);
                acc[i][2] = fma2(ap[i], b23.x, acc[i][2]);
                acc[i][3] = fma2(ap[i], b23.y, acc[i][3]);
            }
        }
        __syncthreads();
    }
    // epilogue: bias + activation + store
    float2 bb[4];
#pragma unroll
    for (int p = 0; p < 4; p++) bb[p] = *(const float2*)(bias + tx * 8 + p * 2);
#pragma unroll
    for (int i = 0; i < 4; i++) {
        float* orow = sOut + (ty * 4 + i) * outStride + tx * 8;
#pragma unroll
        for (int p = 0; p < 4; p++) {
            float2 v = unpack2(acc[i][p]);
            v.x += bb[p].x;
            v.y += bb[p].y;
            if (ACT) { v.x = silu(v.x); v.y = silu(v.y); }
            *(float2*)(orow + p * 2) = v;
        }
    }
    __syncthreads();
}

// ---------------- fused edge kernel ----------------
extern "C" __global__ void __launch_bounds__(NT, 2) edge_kernel(
    int blk_off, int hbuf, const float* __restrict__ edge_fea,
    const int* __restrict__ erow, const int* __restrict__ ecol,
    const float* __restrict__ mW1, const float* __restrict__ mb1,
    const float* __restrict__ mW2, const float* __restrict__ mb2,
    const float* __restrict__ cW1, const float* __restrict__ cb1,
    const float* __restrict__ cW2, const float* __restrict__ cb2) {
    extern __shared__ float sm[];
    float* sIn = sm;                          // 64 x 272
    float* sA = sIn + TILE * SIN_STRIDE;      // 64 x 132
    float* wslab = sA + TILE * SA_STRIDE;     // 2 x 8 x 128
    float* sRij = wslab + 2 * KS * 128;       // 64 x 9
    float* sCm = sRij + TILE * 9;             // 64
    float* sW2c = sCm + TILE;                 // 128
    int* sRow = (int*)(sW2c + 128);           // 64

    const int tid = threadIdx.x;
    const int w = tid >> 5, lane = tid & 31;
    const float* hcur = g_h[hbuf];
    const int eb = (blockIdx.x + blk_off) * TILE;
    const uint32_t sm_sh = (uint32_t)__cvta_generic_to_shared(sm);
    const uint32_t sIn_sh = sm_sh;
    const uint32_t wslab_sh = sm_sh + (TILE * SIN_STRIDE + TILE * SA_STRIDE) * 4;

    if (tid < 128) sW2c[tid] = cW2[tid];

    // ---- gather: each warp handles 8 edges, h/ef via cp.async ----
#pragma unroll
    for (int i = 0; i < 8; i++) {
        int el = w * 8 + i;
        int e = eb + el;
        int r = erow[e], c = ecol[e];
        if (lane == 0) sRow[el] = r;
        cpasync16(sIn_sh + (el * SIN_STRIDE + lane * 4) * 4,
                  hcur + (size_t)r * Hh + lane * 4);
        cpasync16(sIn_sh + (el * SIN_STRIDE + 128 + lane * 4) * 4,
                  hcur + (size_t)c * Hh + lane * 4);
        if (lane < 2)
            cpasync16(sIn_sh + (el * SIN_STRIDE + 256 + lane * 4) * 4,
                      edge_fea + (size_t)e * EDGE_F + lane * 4);
        if (lane < 9) sRij[el * 9 + lane] = g_equ[r * 9 + lane] - g_equ[c * 9 + lane];
        __syncwarp();
        if (lane < 3) {
            float a = sRij[el * 9 + lane];
            float b = sRij[el * 9 + 3 + lane];
            float c2 = sRij[el * 9 + 6 + lane];
            sIn[el * SIN_STRIDE + 264 + lane] = sqrtf(a * a + b * b + c2 * c2);
        }
        if (lane >= 3 && lane < 8) sIn[el * SIN_STRIDE + 264 + lane] = 0.f; // pad 267..271
    }
    cpcommit();
    __syncthreads();

    gemm_tile<true, true>(sIn, SIN_STRIDE, mW1, mb1, MSG_IN, sA, SA_STRIDE,
                          wslab, wslab_sh, tid);
    gemm_tile<false, true>(sA, SA_STRIDE, mW2, mb2, 128, sIn, SIN_STRIDE,
                           wslab, wslab_sh, tid);
    gemm_tile<false, true>(sIn, SIN_STRIDE, cW1, cb1, 128, sA, SA_STRIDE,
                           wslab, wslab_sh, tid);

    // coord scalar: cm[e] = dot(c1[e], cW2) + cb2 (4 lanes per edge)
    {
        int el = w * 8 + (lane >> 2);
        int part = lane & 3;
        const float* base = sA + el * SA_STRIDE + part * 32;
        const float* wb = sW2c + part * 32;
        float s = 0.f;
#pragma unroll
        for (int q = 0; q < 32; q++) s += base[q] * wb[q];
        s += __shfl_xor_sync(0xffffffffu, s, 1);
        s += __shfl_xor_sync(0xffffffffu, s, 2);
        if (part == 0) sCm[el] = s + cb2[0];
    }
    __syncthreads();

    // ---- scatter ----
    for (int idx = tid; idx < TILE * 9; idx += NT) {
        int el = idx / 9, cpt = idx - el * 9;
        float f = sRij[el * 9 + cpt] * sCm[el];
        atomicAdd(&g_fsum[(size_t)sRow[el] * 9 + cpt], f);
    }
    for (int t = tid; t < TILE * 32; t += NT) {
        int el = t >> 5, q = t & 31;
        float4 m = *(const float4*)(sIn + el * SIN_STRIDE + q * 4);
        float* dst = &g_msum[(size_t)sRow[el] * Hh + q * 4];
        asm volatile("red.global.add.v4.f32 [%0], {%1,%2,%3,%4};" ::"l"(dst),
                     "f"(m.x), "f"(m.y), "f"(m.z), "f"(m.w)
                     : "memory");
    }
}

// ---------------- fused node kernel (also re-zeroes msum/fsum) ----------------
extern "C" __global__ void __launch_bounds__(NT, 2) node_kernel(
    int hin, int hout, const float* __restrict__ nW1,
    const float* __restrict__ nb1, const float* __restrict__ nW2,
    const float* __restrict__ nb2, const float* __restrict__ qW1,
    const float* __restrict__ qb1, const float* __restrict__ qW2,
    const float* __restrict__ qb2) {
    extern __shared__ float sm[];
    float* sC = sm;                        // 64 x 260
    float* sA = sC + TILE * SC_STRIDE;     // 64 x 132
    float* wslab = sA + TILE * SA_STRIDE;  // 2 x 8 x 128
    float* sGate = wslab + 2 * KS * 128;   // 64
    float* sW2q = sGate + TILE;            // 128

    const int tid = threadIdx.x;
    const int w = tid >> 5, lane = tid & 31;
    const float* hcur = g_h[hin];
    float* hnext = g_h[hout];
    const int nb = blockIdx.x * TILE;
    const uint32_t sm_sh = (uint32_t)__cvta_generic_to_shared(sm);
    const uint32_t wslab_sh = sm_sh + (TILE * SC_STRIDE + TILE * SA_STRIDE) * 4;

    if (tid < 128) sW2q[tid] = qW2[tid];

#pragma unroll
    for (int i = 0; i < 8; i++) {
        int nl = w * 8 + i;
        int n = nb + nl;
        float4 hv = make_float4(0.f, 0.f, 0.f, 0.f);
        float4 mv = make_float4(0.f, 0.f, 0.f, 0.f);
        if (n < Nn) {
            hv = ((const float4*)(hcur + (size_t)n * Hh))[lane];
            mv = ((const float4*)(g_msum + (size_t)n * Hh))[lane];
            ((float4*)(g_msum + (size_t)n * Hh))[lane] = make_float4(0.f, 0.f, 0.f, 0.f);
        }
        *(float4*)(sC + nl * SC_STRIDE + lane * 4) = hv;
        *(float4*)(sC + nl * SC_STRIDE + 128 + lane * 4) = mv;
    }
    __syncthreads();

    // gate hidden = silu(h @ qW1 + qb1)
    gemm_tile<false, true>(sC, SC_STRIDE, qW1, qb1, 128, sA, SA_STRIDE, wslab,
                           wslab_sh, tid);
    {
        int nl = w * 8 + (lane >> 2);
        int part = lane & 3;
        const float* base = sA + nl * SA_STRIDE + part * 32;
        const float* wb = sW2q + part * 32;
        float s = 0.f;
#pragma unroll
        for (int q = 0; q < 32; q++) s += base[q] * wb[q];
        s += __shfl_xor_sync(0xffffffffu, s, 1);
        s += __shfl_xor_sync(0xffffffffu, s, 2);
        if (part == 0) sGate[nl] = s + qb2[0];
    }
    __syncthreads();

    // equ update: equ = gate*equ + clip(fsum/max(cnt,1)); re-zero fsum
    for (int idx = tid; idx < TILE * 9; idx += NT) {
        int nl = idx / 9, cpt = idx - nl * 9;
        int n = nb + nl;
        if (n < Nn) {
            float cnt = g_cnt[n];
            float inv = 1.f / fmaxf(cnt, 1.f);
            float tf = g_fsum[n * 9 + cpt] * inv;
            g_fsum[n * 9 + cpt] = 0.f;
            tf = fminf(fmaxf(tf, -100.f), 100.f);
            g_equ[n * 9 + cpt] = sGate[nl] * g_equ[n * 9 + cpt] + tf;
        }
    }

    gemm_tile<false, true>(sC, SC_STRIDE, nW1, nb1, 256, sA, SA_STRIDE, wslab,
                           wslab_sh, tid);
    gemm_tile<false, false>(sA, SA_STRIDE, nW2, nb2, 128, sC, SC_STRIDE, wslab,
                            wslab_sh, tid);

#pragma unroll
    for (int i = 0; i < 8; i++) {
        int nl = w * 8 + i;
        int n = nb + nl;
        if (n < Nn) {
            float4 v = *(const float4*)(sC + nl * SC_STRIDE + lane * 4);
            ((float4*)(hnext + (size_t)n * Hh))[lane] = v;
        }
    }
}

// ---------------- small kernels ----------------
extern "C" __global__ void init_kernel(const float* __restrict__ equ_in) {
    int i = blockIdx.x * blockDim.x + threadIdx.x;
    if (i < Nn * 9) g_equ[i] = equ_in[i];
    if (i < Nn) g_cnt[i] = 0.f;
}

extern "C" __global__ void count_kernel(const int* __restrict__ erow) {
    int i = blockIdx.x * blockDim.x + threadIdx.x;
    if (i < Ee) atomicAdd(&g_cnt[erow[i]], 1.f);
}

extern "C" __global__ void embed_kernel(const float* __restrict__ h_in,
                                        const float* __restrict__ W,
                                        const float* __restrict__ b) {
    int n = blockIdx.x * 2 + (threadIdx.x >> 7);
    int j = threadIdx.x & 127;
    if (n >= Nn) return;
    float acc = b[j];
#pragma unroll
    for (int k = 0; k < NODE_F; k++) acc += h_in[n * NODE_F + k] * W[k * 128 + j];
    g_h[0][(size_t)n * Hh + j] = acc;
}

extern "C" __global__ void final_copy_kernel(float* __restrict__ out, int out_size) {
    int i = blockIdx.x * blockDim.x + threadIdx.x;
    int tot = Nn * 9 + Nn * Hh;
    if (i >= tot || i >= out_size) return;
    out[i] = (i < Nn * 9) ? g_equ[i] : g_h[0][i - Nn * 9];
}

// ---------------- launch ----------------
extern "C" void kernel_launch(void* const* d_in, const int* in_sizes, int n_in,
                              void* d_out, int out_size) {
    const float* equ = (const float*)d_in[0];
    const float* h_in = (const float*)d_in[1];
    const float* edge_fea = (const float*)d_in[2];
    const float* embW = (const float*)d_in[3];
    const float* embB = (const float*)d_in[4];
    const float* mW1 = (const float*)d_in[5];
    const float* mb1 = (const float*)d_in[6];
    const float* mW2 = (const float*)d_in[7];
    const float* mb2 = (const float*)d_in[8];
    const float* cW1 = (const float*)d_in[9];
    const float* cb1 = (const float*)d_in[10];
    const float* cW2 = (const float*)d_in[11];
    const float* cb2 = (const float*)d_in[12];
    const float* nW1 = (const float*)d_in[13];
    const float* nb1 = (const float*)d_in[14];
    const float* nW2 = (const float*)d_in[15];
    const float* nb2 = (const float*)d_in[16];
    const float* qW1 = (const float*)d_in[17];
    const float* qb1 = (const float*)d_in[18];
    const float* qW2 = (const float*)d_in[19];
    const float* qb2 = (const float*)d_in[20];
    const int* ei = (const int*)d_in[21];
    const int* erow = ei;
    const int* ecol = ei + Ee;

    const int EDGE_SMEM = (TILE * SIN_STRIDE + TILE * SA_STRIDE + 2 * KS * 128 +
                           TILE * 9 + TILE + 128 + TILE) * 4;  // 114,944 B
    const int NODE_SMEM = (TILE * SC_STRIDE + TILE * SA_STRIDE + 2 * KS * 128 +
                           TILE + 128) * 4;                    // 109,312 B
    cudaFuncSetAttribute(edge_kernel, cudaFuncAttributeMaxDynamicSharedMemorySize, EDGE_SMEM);
    cudaFuncSetAttribute(node_kernel, cudaFuncAttributeMaxDynamicSharedMemorySize, NODE_SMEM);

    init_kernel<<<(Nn * 9 + 255) / 256, 256>>>(equ);
    count_kernel<<<(Ee + 255) / 256, 256>>>(erow);
    embed_kernel<<<Nn / 2, 256>>>(h_in, embW, embB);

    const int NB = Ee / TILE;  // 10000
    for (int L = 0; L < 2; L++) {
        if (L == 0) {
            // split into 4 launches so ncu -s lands on edge_kernel
            for (int qtr = 0; qtr < 4; qtr++)
                edge_kernel<<<NB / 4, NT, EDGE_SMEM>>>(
                    qtr * (NB / 4), L, edge_fea, erow, ecol,
                    mW1 + (size_t)L * MSG_IN * 128, mb1 + L * 128,
                    mW2 + (size_t)L * 128 * 128, mb2 + L * 128,
                    cW1 + (size_t)L * 128 * 128, cb1 + L * 128,
                    cW2 + (size_t)L * 128, cb2 + L);
        } else {
            edge_kernel<<<NB, NT, EDGE_SMEM>>>(
                0, L, edge_fea, erow, ecol,
                mW1 + (size_t)L * MSG_IN * 128, mb1 + L * 128,
                mW2 + (size_t)L * 128 * 128, mb2 + L * 128,
                cW1 + (size_t)L * 128 * 128, cb1 + L * 128,
                cW2 + (size_t)L * 128, cb2 + L);
        }
        node_kernel<<<(Nn + TILE - 1) / TILE, NT, NODE_SMEM>>>(
            L, 1 - L,
            nW1 + (size_t)L * 256 * 128, nb1 + L * 128,
            nW2 + (size_t)L * 128 * 128, nb2 + L * 128,
            qW1 + (size_t)L * 128 * 128, qb1 + L * 128,
            qW2 + (size_t)L * 128, qb2 + L);
    }

    final_copy_kernel<<<(Nn * 9 + Nn * Hh + 255) / 256, 256>>>((float*)d_out, out_size);
}